// round 17
// baseline (speedup 1.0000x reference)
#include <cuda_runtime.h>
#include <cuda_bf16.h>
#include <math.h>

// ---------------- problem constants ----------------
#define T_STEPS 512
#define BATCH   128
#define HDIM    300
#define MCELLS  20
#define ROWS    (BATCH*MCELLS)   // 2560
#define DECAY   0.98f
#define EPS_V   1e-8f

#define NTHREADS 256
#define NJOBS    300    // 3 matrices * 20rt * 5ct, full K per job
#define PJOBS    (T_STEPS*15)   // one-time P precompute jobs
#define NSTAGE   10     // k32 stages over padded K=320 (pairs 0..159)
#define RH       (ROWS*HDIM)
#define PSZ      (BATCH*900)
#define APITCH   160            // pairs per row in A/B tables (zero-padded >=150)
#define WB_MEMSZ  (320*APITCH)  // 51200 per mem matrix
#define WB_POFF   (3*WB_MEMSZ)  // 153600
#define WBTOT     (WB_POFF + 960*APITCH)
#define HSROWS    (T_STEPS*BATCH)  // 65536

// 1 = JAX >= 0.4.30 default (threefry_partitionable)
#define THREEFRY_PARTITIONABLE 1

// ---------------- device state (no allocation anywhere) ----------------
__device__ float g_mem[RH];             // (B,M,H)
__device__ float g_usage[ROWS];         // (B,M)
__device__ float g_HP [RH];             // mem@Ws1[0:300]
__device__ float g_HP2[RH];             // (h*mem)@Ws1[600:900]
__device__ float g_CP [RH];             // mem@Wu[300:600]
__device__ float g_Pall[(size_t)T_STEPS*PSZ];  // h_t@[We1|Ws1mid|Wu0]+biases
__device__ float g_ow[ROWS];
__device__ float g_indv[ROWS];
__device__ unsigned g_WBh[WBTOT];       // B hi bf16-pairs, col-major [col][pair]
__device__ unsigned g_WBl[WBTOT];       // B lo
__device__ unsigned g_AMh[ROWS*APITCH]; // mem split tables   [row][pair]
__device__ unsigned g_AMl[ROWS*APITCH];
__device__ unsigned g_AHh[ROWS*APITCH]; // h*mem split tables
__device__ unsigned g_AHl[ROWS*APITCH];
__device__ unsigned g_HSh[(size_t)HSROWS*APITCH]; // hs split tables (P jobs)
__device__ unsigned g_HSl[(size_t)HSROWS*APITCH];
__device__ float g_bias900[960];        // [be1 | bs1 | bu] (padded)
__device__ unsigned g_count;            // grid-barrier counter
__device__ unsigned g_pctr;             // one-time P job counter
__device__ unsigned g_jobctr[T_STEPS];  // per-step dynamic job counters

// ---------------- dynamic smem tile buffers ----------------
// [buf][k16-block][row][24 shorts]: 16 data + 8 pad; 48B rows, ldmatrix-friendly
struct SmemT {
    unsigned short SAh[2][2][128][24];
    unsigned short SAl[2][2][128][24];
    unsigned short SBh[2][2][64][24];
    unsigned short SBl[2][2][64][24];
};

// ---------------- software grid barrier ----------------
__device__ __forceinline__ void grid_bar(unsigned &target, int nblk) {
    __syncthreads();
    if (threadIdx.x == 0) {
        target += (unsigned)nblk;
        __threadfence();
        atomicAdd(&g_count, 1u);
        volatile unsigned* p = &g_count;
        while (*p < target) { }
        __threadfence();
    }
    __syncthreads();
}

// ---------------- JAX threefry-2x32-20 noise ----------------
__device__ __forceinline__ void tf_round(unsigned &x0, unsigned &x1, int r) {
    x0 += x1;
    x1 = (x1 << r) | (x1 >> (32 - r));
    x1 ^= x0;
}
__device__ __forceinline__ void threefry2x32(unsigned c0, unsigned c1,
                                             unsigned &o0, unsigned &o1) {
    const unsigned k0 = 0u, k1 = 42u, k2 = 0x1BD11BDAu ^ 0u ^ 42u;
    unsigned x0 = c0 + k0, x1 = c1 + k1;
    tf_round(x0,x1,13); tf_round(x0,x1,15); tf_round(x0,x1,26); tf_round(x0,x1,6);
    x0 += k1; x1 += k2 + 1u;
    tf_round(x0,x1,17); tf_round(x0,x1,29); tf_round(x0,x1,16); tf_round(x0,x1,24);
    x0 += k2; x1 += k0 + 2u;
    tf_round(x0,x1,13); tf_round(x0,x1,15); tf_round(x0,x1,26); tf_round(x0,x1,6);
    x0 += k0; x1 += k1 + 3u;
    tf_round(x0,x1,17); tf_round(x0,x1,29); tf_round(x0,x1,16); tf_round(x0,x1,24);
    x0 += k1; x1 += k2 + 4u;
    tf_round(x0,x1,13); tf_round(x0,x1,15); tf_round(x0,x1,26); tf_round(x0,x1,6);
    x0 += k2; x1 += k0 + 5u;
    o0 = x0; o1 = x1;
}
__device__ __forceinline__ float jax_noise(unsigned i) {
    unsigned bits;
#if THREEFRY_PARTITIONABLE
    unsigned o0, o1;
    threefry2x32(0u, i, o0, o1);
    bits = o0 ^ o1;
#else
    const unsigned half = (unsigned)(T_STEPS*BATCH*MCELLS) / 2u;
    unsigned o0, o1;
    if (i < half) { threefry2x32(i, i + half, o0, o1); bits = o0; }
    else          { threefry2x32(i - half, i, o0, o1); bits = o1; }
#endif
    float f = __uint_as_float((bits >> 9) | 0x3f800000u) - 1.0f;
    float u = __fadd_rn(__fmul_rn(f, 0.99f), 0.01f);
    return fmaxf(0.01f, u);
}

// ---------------- warp reductions ----------------
__device__ __forceinline__ float warpSum(float v) {
#pragma unroll
    for (int o = 16; o; o >>= 1) v += __shfl_xor_sync(0xffffffffu, v, o);
    return v;
}
__device__ __forceinline__ float warpMax(float v) {
#pragma unroll
    for (int o = 16; o; o >>= 1) v = fmaxf(v, __shfl_xor_sync(0xffffffffu, v, o));
    return v;
}

// 1-MUFU tanh: __expf (1 MUFU) + bit-trick Newton reciprocal (pure FMA).
// abs err ~1e-6; ax clamped so e stays finite.
__device__ __forceinline__ float tanh_fast(float x) {
    float ax = fminf(fabsf(x), 20.f);
    float e  = __expf(2.f * ax);                 // 1 MUFU
    float d  = e + 1.f;
    float r  = __uint_as_float(0x7EF311C3u - __float_as_uint(d));
    r = r * (2.f - d*r);
    r = r * (2.f - d*r);                         // rel err ~6e-6
    float res = 1.f - 2.f*r;
    return copysignf(res, x);
}

// ---------------- bf16 split helpers ----------------
__device__ __forceinline__ unsigned pack_bf16x2(float e, float o) {
    unsigned r;
    asm("cvt.rn.bf16x2.f32 %0, %1, %2;" : "=r"(r) : "f"(o), "f"(e));
    return r;
}
__device__ __forceinline__ void bsplit(float x, float &hf, float &lf) {
    __nv_bfloat16 h = __float2bfloat16(x);
    hf = __bfloat162float(h);
    lf = x - hf;
}
__device__ __forceinline__ unsigned smem_u32(const void* p) {
    return (unsigned)__cvta_generic_to_shared(p);
}
__device__ __forceinline__ void ldsm4(unsigned r[4], unsigned addr) {
    asm volatile("ldmatrix.sync.aligned.m8n8.x4.shared.b16 {%0,%1,%2,%3}, [%4];"
        : "=r"(r[0]), "=r"(r[1]), "=r"(r[2]), "=r"(r[3]) : "r"(addr));
}
__device__ __forceinline__ void mma_bf16(float c[4],
    unsigned a0, unsigned a1, unsigned a2, unsigned a3,
    unsigned b0, unsigned b1)
{
    asm("mma.sync.aligned.m16n8k16.row.col.f32.bf16.bf16.f32 "
        "{%0,%1,%2,%3}, {%4,%5,%6,%7}, {%8,%9}, {%0,%1,%2,%3};"
        : "+f"(c[0]), "+f"(c[1]), "+f"(c[2]), "+f"(c[3])
        : "r"(a0), "r"(a1), "r"(a2), "r"(a3), "r"(b0), "r"(b1));
}

// ---------------- fast GEMM core (pre-split A/B tables, BM=128/BN=64/BK=32) ----
__device__ __forceinline__ void gemm_fast(
    const unsigned* __restrict__ Ah, const unsigned* __restrict__ Al,
    const unsigned* __restrict__ Bh, const unsigned* __restrict__ Bl,
    float* dst, int ncols, int c0, const float* __restrict__ bias, SmemT* sm)
{
    const int tid = threadIdx.x;
    const int warp = tid >> 5, lane = tid & 31;
    const int m0 = (warp >> 1) * 32;
    const int n0 = (warp & 1) * 32;
    const int lg = lane >> 2, lt = lane & 3;

    const int aRow0 = tid >> 2,        aQ0 = tid & 3;
    const int aRow1 = (tid + 256) >> 2, aQ1 = (tid + 256) & 3;
    const int bCol = tid >> 2,         bQ = tid & 3;
    const size_t aOff0 = (size_t)aRow0*APITCH + (aQ0>>1)*8 + (aQ0&1)*4;
    const size_t aOff1 = (size_t)aRow1*APITCH + (aQ1>>1)*8 + (aQ1&1)*4;
    const size_t bOff  = (size_t)bCol*APITCH + (bQ>>1)*8 + (bQ&1)*4;

    const int lrowA = (lane & 7) + ((lane & 8) ? 8 : 0);
    const int lkA   = (lane & 16) ? 8 : 0;
    unsigned aoff[2];
#pragma unroll
    for (int mi = 0; mi < 2; mi++)
        aoff[mi] = (unsigned)(((m0 + mi*16 + lrowA) * 24 + lkA) * 2);
    const int lrowB = (lane & 7) + ((lane & 16) ? 8 : 0);
    const int lkB   = (lane & 8) ? 8 : 0;
    unsigned boff[2];
#pragma unroll
    for (int nip = 0; nip < 2; nip++)
        boff[nip] = (unsigned)(((n0 + nip*16 + lrowB) * 24 + lkB) * 2);

    unsigned baseSAh[2] = { smem_u32(&sm->SAh[0][0][0][0]), smem_u32(&sm->SAh[1][0][0][0]) };
    unsigned baseSAl[2] = { smem_u32(&sm->SAl[0][0][0][0]), smem_u32(&sm->SAl[1][0][0][0]) };
    unsigned baseSBh[2] = { smem_u32(&sm->SBh[0][0][0][0]), smem_u32(&sm->SBh[1][0][0][0]) };
    unsigned baseSBl[2] = { smem_u32(&sm->SBl[0][0][0][0]), smem_u32(&sm->SBl[1][0][0][0]) };

    float c[2][4][4];
#pragma unroll
    for (int mi = 0; mi < 2; mi++)
#pragma unroll
        for (int ni = 0; ni < 4; ni++)
#pragma unroll
            for (int q = 0; q < 4; q++) c[mi][ni][q] = 0.f;

    uint4 rAh0, rAh1, rAl0, rAl1, rBh, rBl;
    auto ldStage = [&](int s) {
        const size_t kb = (size_t)s * 16;
        rAh0 = *(const uint4*)(Ah + aOff0 + kb);
        rAh1 = *(const uint4*)(Ah + aOff1 + kb);
        rAl0 = *(const uint4*)(Al + aOff0 + kb);
        rAl1 = *(const uint4*)(Al + aOff1 + kb);
        rBh  = *(const uint4*)(Bh + bOff + kb);
        rBl  = *(const uint4*)(Bl + bOff + kb);
    };
    auto stStage = [&](int buf) {
        *(uint4*)&sm->SAh[buf][aQ0>>1][aRow0][(aQ0&1)*8] = rAh0;
        *(uint4*)&sm->SAh[buf][aQ1>>1][aRow1][(aQ1&1)*8] = rAh1;
        *(uint4*)&sm->SAl[buf][aQ0>>1][aRow0][(aQ0&1)*8] = rAl0;
        *(uint4*)&sm->SAl[buf][aQ1>>1][aRow1][(aQ1&1)*8] = rAl1;
        *(uint4*)&sm->SBh[buf][bQ>>1][bCol][(bQ&1)*8] = rBh;
        *(uint4*)&sm->SBl[buf][bQ>>1][bCol][(bQ&1)*8] = rBl;
    };

    ldStage(0);
    stStage(0);
    __syncthreads();

    for (int s = 0; s < NSTAGE; s++) {
        int cur = s & 1;
        bool more = (s + 1 < NSTAGE);
        if (more) ldStage(s + 1);

#pragma unroll
        for (int kb = 0; kb < 2; kb++) {
            unsigned Ahf[2][4], Alf[2][4], Bhf[2][4], Blf[2][4];
#pragma unroll
            for (int mi = 0; mi < 2; mi++) {
                ldsm4(Ahf[mi], baseSAh[cur] + kb*6144u + aoff[mi]);
                ldsm4(Alf[mi], baseSAl[cur] + kb*6144u + aoff[mi]);
            }
#pragma unroll
            for (int nip = 0; nip < 2; nip++) {
                ldsm4(Bhf[nip], baseSBh[cur] + kb*3072u + boff[nip]);
                ldsm4(Blf[nip], baseSBl[cur] + kb*3072u + boff[nip]);
            }
#pragma unroll
            for (int mi = 0; mi < 2; mi++)
#pragma unroll
                for (int ni = 0; ni < 4; ni++) {
                    int nip = ni >> 1, sel = (ni & 1) * 2;
                    unsigned bh0 = Bhf[nip][sel], bh1 = Bhf[nip][sel+1];
                    unsigned bl0 = Blf[nip][sel], bl1 = Blf[nip][sel+1];
                    mma_bf16(c[mi][ni], Ahf[mi][0], Ahf[mi][1], Ahf[mi][2], Ahf[mi][3],
                             bh0, bh1);
                    mma_bf16(c[mi][ni], Ahf[mi][0], Ahf[mi][1], Ahf[mi][2], Ahf[mi][3],
                             bl0, bl1);
                    mma_bf16(c[mi][ni], Alf[mi][0], Alf[mi][1], Alf[mi][2], Alf[mi][3],
                             bh0, bh1);
                }
        }

        if (more) stStage(cur ^ 1);
        __syncthreads();
    }

#pragma unroll
    for (int mi = 0; mi < 2; mi++)
#pragma unroll
        for (int ni = 0; ni < 4; ni++) {
            int row = m0 + mi*16 + lg;
            int col = c0 + n0 + ni*8 + 2*lt;
            float v0 = c[mi][ni][0], v1 = c[mi][ni][1];
            float v2 = c[mi][ni][2], v3 = c[mi][ni][3];
            if (bias) {
                float b0 = bias[col], b1 = bias[col + 1];
                v0 += b0; v2 += b0; v1 += b1; v3 += b1;
            }
            if (col < ncols) {
                dst[row*ncols + col]     = v0;
                dst[(row+8)*ncols + col] = v2;
            }
            if (col + 1 < ncols) {
                dst[row*ncols + col + 1]     = v1;
                dst[(row+8)*ncols + col + 1] = v3;
            }
        }
}

// ---------------- per-step GEMM job ----------------
__device__ __forceinline__ void gemm_job(int job, SmemT* sm)
{
    const int mtype = job / 100;
    int e = job % 100;
    const int r0 = (e / 5) * 128, c0 = (e % 5) * 64;

    const unsigned* Ah = ((mtype == 1) ? g_AHh : g_AMh) + (size_t)r0*APITCH;
    const unsigned* Al = ((mtype == 1) ? g_AHl : g_AMl) + (size_t)r0*APITCH;
    const unsigned* Bh = g_WBh + mtype * WB_MEMSZ + (size_t)c0*APITCH;
    const unsigned* Bl = g_WBl + mtype * WB_MEMSZ + (size_t)c0*APITCH;

    float* dstbase = (mtype == 0) ? g_HP : (mtype == 1) ? g_HP2 : g_CP;
    gemm_fast(Ah, Al, Bh, Bl, dstbase + r0*300, 300, c0, (const float*)0, sm);
}

// ---------------- one-time P GEMM job (biases folded) ----------------
__device__ __forceinline__ void pgemm_job(int job, SmemT* sm)
{
    const int t = job / 15;
    const int c0 = (job % 15) * 64;
    const unsigned* Ah = g_HSh + (size_t)t*128*APITCH;
    const unsigned* Al = g_HSl + (size_t)t*128*APITCH;
    const unsigned* Bh = g_WBh + WB_POFF + (size_t)c0*APITCH;
    const unsigned* Bl = g_WBl + WB_POFF + (size_t)c0*APITCH;
    gemm_fast(Ah, Al, Bh, Bl, g_Pall + (size_t)t*PSZ, 900, c0, g_bias900, sm);
}

// ---------------- gating job (block handles batch b; float4 streams) ---------
__device__ __forceinline__ void gate_job(
    int b, int t,
    const float* __restrict__ mask,
    const float* __restrict__ We2, const float* __restrict__ be2,
    const float* __restrict__ Ws2, const float* __restrict__ bs2,
    const float* __restrict__ Ws1,
    float* __restrict__ out,
    float (&s_sim)[MCELLS], float (&s_usage)[MCELLS],
    float (&s_red)[8], float &s_ent)
{
    const int tid = threadIdx.x;
    const int warp = tid >> 5, lane = tid & 31;

    const float4* P4   = (const float4*)(g_Pall + (size_t)t*PSZ + b*900);
    const float4* WU4  = (const float4*)(Ws1 + 900*300);
    const float4* We24 = (const float4*)We2;
    const float4* Ws24 = (const float4*)Ws2;
    const float4* HP4  = (const float4*)g_HP;
    const float4* HP24 = (const float4*)g_HP2;

    if (tid < MCELLS) s_usage[tid] = g_usage[b*MCELLS + tid];
    __syncthreads();

    // ---- entity prob (be1 folded into P) ----
    float acc = 0.f;
    for (int q = tid; q < 75; q += NTHREADS) {
        float4 p = P4[q], w = We24[q];
        acc += fmaxf(p.x, 0.f)*w.x + fmaxf(p.y, 0.f)*w.y
             + fmaxf(p.z, 0.f)*w.z + fmaxf(p.w, 0.f)*w.w;
    }
    acc = warpSum(acc);
    if (lane == 0) s_red[warp] = acc;
    __syncthreads();
    if (tid == 0) {
        float s = 0.f;
        for (int w = 0; w < 8; w++) s += s_red[w];
        float score = s + be2[0];
        float sig = 1.f / (1.f + expf(-score));
        s_ent = sig * mask[(size_t)t*BATCH + b];
    }

    // ---- sim[m] (bs1 folded into P[300:600]) ----
    for (int m = warp; m < MCELLS; m += 8) {
        float u = s_usage[m];
        const int ro4 = (b*MCELLS + m)*75;
        float a = 0.f;
        for (int q = lane; q < 75; q += 32) {
            float4 hp = HP4[ro4+q], hp2 = HP24[ro4+q];
            float4 p = P4[75+q], wu = WU4[q], w2 = Ws24[q];
            a += fmaxf(hp.x + hp2.x + p.x + u*wu.x, 0.f) * w2.x
               + fmaxf(hp.y + hp2.y + p.y + u*wu.y, 0.f) * w2.y
               + fmaxf(hp.z + hp2.z + p.z + u*wu.z, 0.f) * w2.z
               + fmaxf(hp.w + hp2.w + p.w + u*wu.w, 0.f) * w2.w;
        }
        a = warpSum(a);
        if (lane == 0) s_sim[m] = a + bs2[0];
    }
    __syncthreads();

    // ---- gating (warp 0; lane = slot 0..20) ----
    if (warp == 0) {
        const unsigned FULL = 0xffffffffu;
        const int m = lane;
        const float NEG_INF = -INFINITY;
        float usg  = (m < MCELLS) ? s_usage[m] : 0.f;
        float simv = (m < MCELLS) ? s_sim[m]   : 0.f;

        float comb;
        if (m < MCELLS)       comb = (usg > 0.f) ? simv : -10000.f;
        else if (m == MCELLS) comb = 0.f;
        else                  comb = NEG_INF;
        float mx   = warpMax(comb);
        float ex   = (m <= MCELLS) ? expf(comb - mx) : 0.f;
        float esum = warpSum(ex);
        float prob = ex / esum;
        float mult = (m < MCELLS) ? ((usg > 0.f) ? 1.f : 0.f)
                                  : ((m == MCELLS) ? 1.f : 0.f);
        float maskedp = prob * mult;
        float msum = warpSum(maskedp);
        float nrm  = maskedp / (msum + EPS_V);
        float co   = s_ent * nrm;
        float ow_base = __shfl_sync(FULL, co, MCELLS);
        float indv = (m < MCELLS) ? co : 0.f;

        float s2  = (m < MCELLS) ? simv : NEG_INF;
        float mx2 = warpMax(s2);
        float e2  = (m < MCELLS) ? expf(simv - mx2) : 0.f;
        float es2 = warpSum(e2);
        float nsim = e2 / es2;

        float ow_score = (m < MCELLS)
            ? ((usg == 0.f ? nsim * 100000.f : 0.f) + (1.f - usg))
            : NEG_INF;
        float maxv = warpMax(ow_score);
        float nz   = (m < MCELLS && ow_score == maxv)
            ? jax_noise((unsigned)(((size_t)t*BATCH + b)*MCELLS + m)) : 0.f;
        float nzmax = warpMax(nz);
        unsigned ballot = __ballot_sync(FULL, (m < MCELLS) && (nz == nzmax));
        int idx = __ffs(ballot) - 1;

        float ow = (m == idx) ? ow_base : 0.f;
        float nu = fminf(1.f, ow + indv + DECAY * usg);

        float* out_ent = out;
        float* out_usg = out + (size_t)T_STEPS*BATCH;
        float* out_crf = out_usg + (size_t)T_STEPS*BATCH*MCELLS;
        float* out_ow  = out_crf + (size_t)T_STEPS*BATCH*MCELLS;
        if (m < MCELLS) {
            g_ow[b*MCELLS + m]    = ow;
            g_indv[b*MCELLS + m]  = indv;
            g_usage[b*MCELLS + m] = nu;
            size_t o = ((size_t)t*BATCH + b)*MCELLS + m;
            out_usg[o] = nu;
            out_crf[o] = indv * (1.f - EPS_V) + EPS_V;
            out_ow[o]  = ow   * (1.f - EPS_V) + EPS_V;
        }
        if (m == 0)
            out_ent[(size_t)t*BATCH + b] = s_ent * (1.f - EPS_V) + EPS_V;
    }
}

// ---------------- persistent kernel ----------------
__global__ __launch_bounds__(NTHREADS, 2) void k_persist(
    const float* __restrict__ hs, const float* __restrict__ mask,
    const float* __restrict__ We1, const float* __restrict__ be1,
    const float* __restrict__ We2, const float* __restrict__ be2,
    const float* __restrict__ Ws1, const float* __restrict__ bs1,
    const float* __restrict__ Ws2, const float* __restrict__ bs2,
    const float* __restrict__ Wu,  const float* __restrict__ bu,
    float* __restrict__ out, int nblk)
{
    extern __shared__ char smem_raw[];
    SmemT* sm = (SmemT*)smem_raw;

    __shared__ float s_sim[MCELLS], s_usage[MCELLS];
    __shared__ float s_red[8];
    __shared__ float s_ent;
    __shared__ int s_job;

    const int tid = threadIdx.x;
    unsigned target = 0;

    // ---- one-time: bias vector ----
    for (int j = blockIdx.x*NTHREADS + tid; j < 960; j += nblk*NTHREADS) {
        float v = 0.f;
        if (j < 300)      v = be1[j];
        else if (j < 600) v = bs1[j - 300];
        else if (j < 900) v = bu[j - 600];
        g_bias900[j] = v;
    }
    // ---- one-time: col-major padded B split tables ----
    for (int idx = blockIdx.x*NTHREADS + tid; idx < WBTOT; idx += nblk*NTHREADS) {
        float v0 = 0.f, v1 = 0.f;
        if (idx < WB_POFF) {
            int mtype = idx / WB_MEMSZ;
            int e = idx % WB_MEMSZ;
            int col = e / APITCH, p = e % APITCH;
            int k0 = 2*p, k1 = 2*p + 1;
            if (col < 300 && k0 < 300) {
                if (mtype == 0)      { v0 = Ws1[k0*300 + col];
                                       if (k1 < 300) v1 = Ws1[k1*300 + col]; }
                else if (mtype == 1) { v0 = Ws1[(600+k0)*300 + col];
                                       if (k1 < 300) v1 = Ws1[(600+k1)*300 + col]; }
                else                 { v0 = Wu[(300+k0)*300 + col];
                                       if (k1 < 300) v1 = Wu[(300+k1)*300 + col]; }
            }
        } else {
            int e = idx - WB_POFF;
            int col = e / APITCH, p = e % APITCH;
            int k0 = 2*p, k1 = 2*p + 1;
            if (col < 900 && k0 < 300) {
                int role = col / 300, jc = col - role*300;
                if (role == 0)      { v0 = We1[k0*300 + jc];
                                      if (k1 < 300) v1 = We1[k1*300 + jc]; }
                else if (role == 1) { v0 = Ws1[(300+k0)*300 + jc];
                                      if (k1 < 300) v1 = Ws1[(300+k1)*300 + jc]; }
                else                { v0 = Wu[k0*300 + jc];
                                      if (k1 < 300) v1 = Wu[k1*300 + jc]; }
            }
        }
        float h0,l0,h1,l1;
        bsplit(v0, h0, l0);
        bsplit(v1, h1, l1);
        g_WBh[idx] = pack_bf16x2(h0, h1);
        g_WBl[idx] = pack_bf16x2(l0, l1);
    }
    // ---- one-time: hs split tables ----
    for (size_t idx = blockIdx.x*NTHREADS + tid; idx < (size_t)HSROWS*APITCH;
         idx += (size_t)nblk*NTHREADS) {
        size_t row = idx / APITCH;
        int p = (int)(idx % APITCH);
        int k0 = 2*p, k1 = 2*p + 1;
        float v0 = 0.f, v1 = 0.f;
        if (k0 < 300) {
            v0 = hs[row*HDIM + k0];
            if (k1 < 300) v1 = hs[row*HDIM + k1];
        }
        float h0,l0,h1,l1;
        bsplit(v0, h0, l0);
        bsplit(v1, h1, l1);
        g_HSh[idx] = pack_bf16x2(h0, h1);
        g_HSl[idx] = pack_bf16x2(l0, l1);
    }
    grid_bar(target, nblk);

    // ---- one-time: precompute P for ALL steps ----
    for (;;) {
        if (tid == 0) s_job = (int)atomicAdd(&g_pctr, 1u);
        __syncthreads();
        int job = s_job;
        __syncthreads();
        if (job >= PJOBS) break;
        pgemm_job(job, sm);
    }
    grid_bar(target, nblk);

    for (int t = 0; t < T_STEPS; t++) {
        // ---- phase A: mem-dependent GEMMs ----
        for (;;) {
            if (tid == 0) s_job = (int)atomicAdd(&g_jobctr[t], 1u);
            __syncthreads();
            int job = s_job;
            __syncthreads();
            if (job >= NJOBS) break;
            gemm_job(job, sm);
        }
        grid_bar(target, nblk);

        // ---- phase B: gate only (blocks 0..127) ----
        if (blockIdx.x < BATCH)
            gate_job(blockIdx.x, t, mask, We2, be2, Ws2, bs2,
                     Ws1, out, s_sim, s_usage, s_red, s_ent);
        grid_bar(target, nblk);

        // ---- phase C: mem update with inline cand + next-step A split build ----
        {
            const float4* hb4 = (const float4*)(hs + (size_t)t*BATCH*HDIM);
            const float4* hn4 = (const float4*)(hs + (size_t)(t+1)*BATCH*HDIM);
            const bool more = (t + 1 < T_STEPS);
            const float4* CP4 = (const float4*)g_CP;
            const float4* Pt4 = (const float4*)(g_Pall + (size_t)t*PSZ);
            float4* mem4 = (float4*)g_mem;
            const int total = ROWS * 75;
            for (int idx = blockIdx.x*NTHREADS + tid; idx < total;
                 idx += nblk*NTHREADS) {
                int r  = idx / 75;
                int jq = idx - r*75;
                int b  = r / MCELLS;
                float owv = g_ow[r], iv = g_indv[r];
                float coef = 1.f - owv - iv;
                float4 ca = CP4[idx];
                float4 pa = Pt4[b*225 + 150 + jq];   // bu folded
                float4 cd;
                cd.x = tanh_fast(ca.x + pa.x);
                cd.y = tanh_fast(ca.y + pa.y);
                cd.z = tanh_fast(ca.z + pa.z);
                cd.w = tanh_fast(ca.w + pa.w);
                float4 h  = hb4[b*75 + jq];
                float4 mo = mem4[idx];
                float4 res;
                res.x = owv*h.x + coef*mo.x + iv*cd.x;
                res.y = owv*h.y + coef*mo.y + iv*cd.y;
                res.z = owv*h.z + coef*mo.z + iv*cd.z;
                res.w = owv*h.w + coef*mo.w + iv*cd.w;
                mem4[idx] = res;
                if (more) {
                    size_t to = (size_t)r*APITCH + jq*2;
                    float hx,lx,hy,ly,hz,lz,hw,lw;
                    bsplit(res.x,hx,lx); bsplit(res.y,hy,ly);
                    bsplit(res.z,hz,lz); bsplit(res.w,hw,lw);
                    *(uint2*)&g_AMh[to] = make_uint2(pack_bf16x2(hx,hy), pack_bf16x2(hz,hw));
                    *(uint2*)&g_AMl[to] = make_uint2(pack_bf16x2(lx,ly), pack_bf16x2(lz,lw));
                    float4 hn = hn4[b*75 + jq];
                    float mx2 = res.x*hn.x, my2 = res.y*hn.y;
                    float mz2 = res.z*hn.z, mw2 = res.w*hn.w;
                    bsplit(mx2,hx,lx); bsplit(my2,hy,ly);
                    bsplit(mz2,hz,lz); bsplit(mw2,hw,lw);
                    *(uint2*)&g_AHh[to] = make_uint2(pack_bf16x2(hx,hy), pack_bf16x2(hz,hw));
                    *(uint2*)&g_AHl[to] = make_uint2(pack_bf16x2(lx,ly), pack_bf16x2(lz,lw));
                }
            }
        }
        grid_bar(target, nblk);
    }
}

extern "C" void kernel_launch(void* const* d_in, const int* in_sizes, int n_in,
                              void* d_out, int out_size) {
    const float* hs   = (const float*)d_in[0];
    const float* mask = (const float*)d_in[1];
    const float* We1  = (const float*)d_in[2];
    const float* be1  = (const float*)d_in[3];
    const float* We2  = (const float*)d_in[4];
    const float* be2  = (const float*)d_in[5];
    const float* Ws1  = (const float*)d_in[6];
    const float* bs1  = (const float*)d_in[7];
    const float* Ws2  = (const float*)d_in[8];
    const float* bs2  = (const float*)d_in[9];
    const float* Wu   = (const float*)d_in[10];
    const float* bu   = (const float*)d_in[11];
    float* out = (float*)d_out;

    const int smemsz = (int)sizeof(SmemT);
    cudaFuncSetAttribute(k_persist, cudaFuncAttributeMaxDynamicSharedMemorySize,
                         smemsz);

    int smcount = 148;
    cudaDeviceGetAttribute(&smcount, cudaDevAttrMultiProcessorCount, 0);
    int maxb = 1;
    cudaOccupancyMaxActiveBlocksPerMultiprocessor(&maxb, k_persist, NTHREADS,
                                                  smemsz);
    if (maxb > 2) maxb = 2;
    if (maxb < 1) maxb = 1;
    int nblk = maxb * smcount;

    void *pmem, *pusg, *pcnt, *pjob, *ppc, *pamh, *paml, *pahh, *pahl;
    cudaGetSymbolAddress(&pmem, g_mem);
    cudaGetSymbolAddress(&pusg, g_usage);
    cudaGetSymbolAddress(&pcnt, g_count);
    cudaGetSymbolAddress(&pjob, g_jobctr);
    cudaGetSymbolAddress(&ppc,  g_pctr);
    cudaGetSymbolAddress(&pamh, g_AMh);
    cudaGetSymbolAddress(&paml, g_AMl);
    cudaGetSymbolAddress(&pahh, g_AHh);
    cudaGetSymbolAddress(&pahl, g_AHl);
    cudaMemsetAsync(pmem, 0, sizeof(float)*(size_t)RH);
    cudaMemsetAsync(pusg, 0, sizeof(float)*(size_t)ROWS);
    cudaMemsetAsync(pcnt, 0, sizeof(unsigned));
    cudaMemsetAsync(ppc,  0, sizeof(unsigned));
    cudaMemsetAsync(pjob, 0, sizeof(unsigned)*T_STEPS);
    cudaMemsetAsync(pamh, 0, sizeof(unsigned)*(size_t)ROWS*APITCH);
    cudaMemsetAsync(paml, 0, sizeof(unsigned)*(size_t)ROWS*APITCH);
    cudaMemsetAsync(pahh, 0, sizeof(unsigned)*(size_t)ROWS*APITCH);
    cudaMemsetAsync(pahl, 0, sizeof(unsigned)*(size_t)ROWS*APITCH);

    k_persist<<<nblk, NTHREADS, smemsz>>>(hs, mask, We1, be1, We2, be2,
                                          Ws1, bs1, Ws2, bs2, Wu, bu, out, nblk);
}